// round 13
// baseline (speedup 1.0000x reference)
#include <cuda_runtime.h>
#include <math.h>

#define L_SEQ   4096
#define DMODEL  2048
#define NH      16
#define NKV     4
#define HD      128
#define WINDOW  1024
#define SOFTMAX_SCALE 0.08838834764831845f  // 1/sqrt(128)

// -------- scratch (static device globals; no runtime allocation) --------
__device__ float g_Q[L_SEQ * NH  * HD];   // 32 MB
__device__ float g_K[L_SEQ * NKV * HD];   //  8 MB
__device__ float g_V[L_SEQ * NKV * HD];   //  8 MB
__device__ float g_att[L_SEQ * NH * HD];  // 32 MB

// ============================================================================
// SGEMM: C[M,N] = A[M,K] @ B[K,N], all row-major fp32.
// 128x128 block tile, BK=16, 256 threads, 8x8 register micro-tile.
// ============================================================================
__global__ __launch_bounds__(256, 2) void sgemm_kernel(
    const float* __restrict__ A, const float* __restrict__ B,
    float* __restrict__ C, int M, int N, int K)
{
    __shared__ float As[16][132];   // A transposed: As[k][m], padded
    __shared__ float Bs[16][128];   // Bs[k][n]

    const int tid = threadIdx.x;
    const int ty  = tid >> 4;       // 0..15 -> row group
    const int tx  = tid & 15;       // 0..15 -> col group
    const int m0  = blockIdx.y * 128;
    const int n0  = blockIdx.x * 128;

    const int arow = tid >> 2;          // 0..63
    const int acol = (tid & 3) << 2;    // 0,4,8,12
    const int brow = tid >> 5;          // 0..7
    const int bcol = (tid & 31) << 2;   // 0..124

    float acc[8][8];
    #pragma unroll
    for (int i = 0; i < 8; i++)
        #pragma unroll
        for (int j = 0; j < 8; j++) acc[i][j] = 0.f;

    for (int k0 = 0; k0 < K; k0 += 16) {
        float4 a0 = *(const float4*)(A + (size_t)(m0 + arow)      * K + k0 + acol);
        float4 a1 = *(const float4*)(A + (size_t)(m0 + arow + 64) * K + k0 + acol);
        float4 b0 = *(const float4*)(B + (size_t)(k0 + brow)     * N + n0 + bcol);
        float4 b1 = *(const float4*)(B + (size_t)(k0 + brow + 8) * N + n0 + bcol);
        __syncthreads();
        As[acol + 0][arow] = a0.x; As[acol + 1][arow] = a0.y;
        As[acol + 2][arow] = a0.z; As[acol + 3][arow] = a0.w;
        As[acol + 0][arow + 64] = a1.x; As[acol + 1][arow + 64] = a1.y;
        As[acol + 2][arow + 64] = a1.z; As[acol + 3][arow + 64] = a1.w;
        *(float4*)&Bs[brow][bcol]     = b0;
        *(float4*)&Bs[brow + 8][bcol] = b1;
        __syncthreads();

        #pragma unroll
        for (int kk = 0; kk < 16; kk++) {
            float af[8], bf[8];
            *(float4*)&af[0] = *(const float4*)&As[kk][ty * 8];
            *(float4*)&af[4] = *(const float4*)&As[kk][ty * 8 + 4];
            *(float4*)&bf[0] = *(const float4*)&Bs[kk][tx * 8];
            *(float4*)&bf[4] = *(const float4*)&Bs[kk][tx * 8 + 4];
            #pragma unroll
            for (int i = 0; i < 8; i++)
                #pragma unroll
                for (int j = 0; j < 8; j++)
                    acc[i][j] = fmaf(af[i], bf[j], acc[i][j]);
        }
    }

    #pragma unroll
    for (int i = 0; i < 8; i++) {
        float* cptr = C + (size_t)(m0 + ty * 8 + i) * N + n0 + tx * 8;
        *(float4*)cptr       = make_float4(acc[i][0], acc[i][1], acc[i][2], acc[i][3]);
        *(float4*)(cptr + 4) = make_float4(acc[i][4], acc[i][5], acc[i][6], acc[i][7]);
    }
}

// ============================================================================
// Fused RMSNorm + RoPE. One block of 128 threads per (token, head) row.
// X is (L, heads*HD) row-major; row = token*heads + head.
// ============================================================================
__global__ __launch_bounds__(128) void norm_rope_kernel(
    float* __restrict__ X, const float* __restrict__ scale,
    const int* __restrict__ positions, int heads)
{
    __shared__ float xs[HD];
    __shared__ float red[4];

    const int row   = blockIdx.x;
    const int token = row / heads;
    const int d     = threadIdx.x;
    float* ptr = X + (size_t)row * HD;

    float v  = ptr[d];
    float ss = v * v;
    #pragma unroll
    for (int off = 16; off > 0; off >>= 1)
        ss += __shfl_xor_sync(0xffffffffu, ss, off);
    if ((d & 31) == 0) red[d >> 5] = ss;
    __syncthreads();
    float tot = red[0] + red[1] + red[2] + red[3];
    float xn  = v * rsqrtf(tot * (1.0f / HD) + 1e-6f) * scale[d];
    xs[d] = xn;
    __syncthreads();

    const int   pos    = positions[token];
    const int   i      = d & 63;
    // timescale = 10000^(i/64)  ->  1/ts = exp2(-i * log2(10000)/64)
    const float inv_ts = exp2f(-(float)i * 0.20762050593046014f);
    const float ang    = (float)pos * inv_ts;
    float s, c;
    sincosf(ang, &s, &c);
    const float partner = xs[d ^ 64];
    const float out = (d < 64) ? (xn * c - partner * s)
                               : (xn * c + partner * s);
    ptr[d] = out;
}

// ============================================================================
// Sliding-window causal flash attention (fp32, online softmax).
// Block = (64 queries, 1 head); 256 threads as 16x16; 4x4 score micro-tile
// (strided: rows ty+16*ii, cols tx+16*jj), P staged through shared memory,
// 4x8 output micro-tile. GQA: q head h -> kv head h/4.
// ============================================================================
#define ATTN_SMEM_FLOATS (3 * 64 * 132 + 64 * 65)
#define ATTN_SMEM_BYTES  (ATTN_SMEM_FLOATS * 4)

__global__ __launch_bounds__(256) void attn_kernel(
    const float* __restrict__ Q, const float* __restrict__ K,
    const float* __restrict__ V, float* __restrict__ O)
{
    extern __shared__ float sm[];
    float (*Qs)[132] = (float (*)[132])sm;
    float (*Ks)[132] = (float (*)[132])(sm + 64 * 132);
    float (*Vs)[132] = (float (*)[132])(sm + 2 * 64 * 132);
    float (*Ps)[65]  = (float (*)[65]) (sm + 3 * 64 * 132);

    const int qt  = blockIdx.x;
    const int h   = blockIdx.y;
    const int q0  = qt * 64;
    const int g   = h >> 2;             // kv head (rep = 4)
    const int tid = threadIdx.x;
    const int ty  = tid >> 4;
    const int tx  = tid & 15;
    const int li  = tid >> 5;           // load row base (0..7)
    const int ld  = (tid & 31) * 4;     // load col (0..124)

    #pragma unroll
    for (int r = 0; r < 8; r++) {
        *(float4*)&Qs[li + r * 8][ld] =
            *(const float4*)(Q + (size_t)(q0 + li + r * 8) * (NH * HD) + h * HD + ld);
    }

    float m[4], l[4], o[4][8];
    #pragma unroll
    for (int ii = 0; ii < 4; ii++) {
        m[ii] = -1e30f; l[ii] = 0.f;
        #pragma unroll
        for (int c = 0; c < 8; c++) o[ii][c] = 0.f;
    }

    const int lo  = q0 - (WINDOW - 1);
    const int kt0 = (lo > 0) ? (lo >> 6) : 0;

    for (int kt = kt0; kt <= qt; kt++) {
        const int k0 = kt * 64;
        __syncthreads();
        #pragma unroll
        for (int r = 0; r < 8; r++) {
            const size_t off = (size_t)(k0 + li + r * 8) * (NKV * HD) + g * HD + ld;
            *(float4*)&Ks[li + r * 8][ld] = *(const float4*)(K + off);
            *(float4*)&Vs[li + r * 8][ld] = *(const float4*)(V + off);
        }
        __syncthreads();

        // ---- S = Q K^T ----
        float s[4][4];
        #pragma unroll
        for (int ii = 0; ii < 4; ii++)
            #pragma unroll
            for (int jj = 0; jj < 4; jj++) s[ii][jj] = 0.f;

        #pragma unroll 8
        for (int d = 0; d < HD; d += 4) {
            float4 qf[4], kf[4];
            #pragma unroll
            for (int ii = 0; ii < 4; ii++) qf[ii] = *(const float4*)&Qs[ty + 16 * ii][d];
            #pragma unroll
            for (int jj = 0; jj < 4; jj++) kf[jj] = *(const float4*)&Ks[tx + 16 * jj][d];
            #pragma unroll
            for (int ii = 0; ii < 4; ii++)
                #pragma unroll
                for (int jj = 0; jj < 4; jj++) {
                    s[ii][jj] = fmaf(qf[ii].x, kf[jj].x, s[ii][jj]);
                    s[ii][jj] = fmaf(qf[ii].y, kf[jj].y, s[ii][jj]);
                    s[ii][jj] = fmaf(qf[ii].z, kf[jj].z, s[ii][jj]);
                    s[ii][jj] = fmaf(qf[ii].w, kf[jj].w, s[ii][jj]);
                }
        }

        // ---- mask + online softmax ----
        #pragma unroll
        for (int ii = 0; ii < 4; ii++) {
            const int qi = q0 + ty + 16 * ii;
            float rmax = -1e30f;
            #pragma unroll
            for (int jj = 0; jj < 4; jj++) {
                const int kj = k0 + tx + 16 * jj;
                const bool ok = (kj <= qi) && (kj > qi - WINDOW);
                const float val = ok ? s[ii][jj] * SOFTMAX_SCALE : -1e30f;
                s[ii][jj] = val;
                rmax = fmaxf(rmax, val);
            }
            #pragma unroll
            for (int off = 8; off > 0; off >>= 1)
                rmax = fmaxf(rmax, __shfl_xor_sync(0xffffffffu, rmax, off));

            const float mn   = fmaxf(m[ii], rmax);
            const float corr = __expf(m[ii] - mn);
            m[ii] = mn;
            l[ii] *= corr;
            #pragma unroll
            for (int c = 0; c < 8; c++) o[ii][c] *= corr;

            float rsum = 0.f;
            #pragma unroll
            for (int jj = 0; jj < 4; jj++) {
                const float p = (s[ii][jj] < -1e29f) ? 0.f : __expf(s[ii][jj] - mn);
                Ps[ty + 16 * ii][tx + 16 * jj] = p;
                rsum += p;
            }
            #pragma unroll
            for (int off = 8; off > 0; off >>= 1)
                rsum += __shfl_xor_sync(0xffffffffu, rsum, off);
            l[ii] += rsum;
        }
        __syncthreads();

        // ---- O += P V ----
        #pragma unroll 4
        for (int j = 0; j < 64; j++) {
            const float4 v0 = *(const float4*)&Vs[j][tx * 8];
            const float4 v1 = *(const float4*)&Vs[j][tx * 8 + 4];
            #pragma unroll
            for (int ii = 0; ii < 4; ii++) {
                const float p = Ps[ty + 16 * ii][j];
                o[ii][0] = fmaf(p, v0.x, o[ii][0]);
                o[ii][1] = fmaf(p, v0.y, o[ii][1]);
                o[ii][2] = fmaf(p, v0.z, o[ii][2]);
                o[ii][3] = fmaf(p, v0.w, o[ii][3]);
                o[ii][4] = fmaf(p, v1.x, o[ii][4]);
                o[ii][5] = fmaf(p, v1.y, o[ii][5]);
                o[ii][6] = fmaf(p, v1.z, o[ii][6]);
                o[ii][7] = fmaf(p, v1.w, o[ii][7]);
            }
        }
    }

    #pragma unroll
    for (int ii = 0; ii < 4; ii++) {
        const float inv = 1.0f / l[ii];
        float* optr = O + (size_t)(q0 + ty + 16 * ii) * (NH * HD) + h * HD + tx * 8;
        *(float4*)optr = make_float4(o[ii][0] * inv, o[ii][1] * inv,
                                     o[ii][2] * inv, o[ii][3] * inv);
        *(float4*)(optr + 4) = make_float4(o[ii][4] * inv, o[ii][5] * inv,
                                           o[ii][6] * inv, o[ii][7] * inv);
    }
}

// ============================================================================
// launch
// ============================================================================
extern "C" void kernel_launch(void* const* d_in, const int* in_sizes, int n_in,
                              void* d_out, int out_size)
{
    const float* x   = (const float*)d_in[0];
    const int*   pos = (const int*)  d_in[1];
    const float* Wq  = (const float*)d_in[2];
    const float* Wk  = (const float*)d_in[3];
    const float* Wv  = (const float*)d_in[4];
    const float* Wo  = (const float*)d_in[5];
    const float* qsc = (const float*)d_in[6];
    const float* ksc = (const float*)d_in[7];
    float* out = (float*)d_out;

    float *Qp, *Kp, *Vp, *Ap;
    cudaGetSymbolAddress((void**)&Qp, g_Q);
    cudaGetSymbolAddress((void**)&Kp, g_K);
    cudaGetSymbolAddress((void**)&Vp, g_V);
    cudaGetSymbolAddress((void**)&Ap, g_att);

    // QKV projections
    sgemm_kernel<<<dim3(NH * HD / 128,  L_SEQ / 128), 256>>>(x, Wq, Qp, L_SEQ, NH * HD,  DMODEL);
    sgemm_kernel<<<dim3(NKV * HD / 128, L_SEQ / 128), 256>>>(x, Wk, Kp, L_SEQ, NKV * HD, DMODEL);
    sgemm_kernel<<<dim3(NKV * HD / 128, L_SEQ / 128), 256>>>(x, Wv, Vp, L_SEQ, NKV * HD, DMODEL);

    // RMSNorm + RoPE on Q and K
    norm_rope_kernel<<<L_SEQ * NH,  HD>>>(Qp, qsc, pos, NH);
    norm_rope_kernel<<<L_SEQ * NKV, HD>>>(Kp, ksc, pos, NKV);

    // sliding-window attention
    cudaFuncSetAttribute(attn_kernel, cudaFuncAttributeMaxDynamicSharedMemorySize,
                         ATTN_SMEM_BYTES);
    attn_kernel<<<dim3(L_SEQ / 64, NH), 256, ATTN_SMEM_BYTES>>>(Qp, Kp, Vp, Ap);

    // output projection straight into d_out
    sgemm_kernel<<<dim3(DMODEL / 128, L_SEQ / 128), 256>>>(Ap, Wo, out, L_SEQ, DMODEL, NH * HD);
}

// round 14
// speedup vs baseline: 1.0014x; 1.0014x over previous
#include <cuda_runtime.h>
#include <math.h>

#define L_SEQ   4096
#define DMODEL  2048
#define NH      16
#define NKV     4
#define HD      128
#define WINDOW  1024
#define SOFTMAX_SCALE 0.08838834764831845f  // 1/sqrt(128)

// -------- scratch (static device globals; no runtime allocation) --------
__device__ float g_Q[L_SEQ * NH  * HD];   // 32 MB
__device__ float g_K[L_SEQ * NKV * HD];   //  8 MB
__device__ float g_V[L_SEQ * NKV * HD];   //  8 MB
__device__ float g_att[L_SEQ * NH * HD];  // 32 MB

// ============================================================================
// SGEMM: C[M,N] = A[M,K] @ B[K,N], all row-major fp32.
// 128x128 block tile, BK=16, 256 threads, 8x8 register micro-tile.
// ============================================================================
__global__ __launch_bounds__(256, 2) void sgemm_kernel(
    const float* __restrict__ A, const float* __restrict__ B,
    float* __restrict__ C, int M, int N, int K)
{
    __shared__ float As[16][132];   // A transposed: As[k][m], padded
    __shared__ float Bs[16][128];   // Bs[k][n]

    const int tid = threadIdx.x;
    const int ty  = tid >> 4;       // 0..15 -> row group
    const int tx  = tid & 15;       // 0..15 -> col group
    const int m0  = blockIdx.y * 128;
    const int n0  = blockIdx.x * 128;

    const int arow = tid >> 2;          // 0..63
    const int acol = (tid & 3) << 2;    // 0,4,8,12
    const int brow = tid >> 5;          // 0..7
    const int bcol = (tid & 31) << 2;   // 0..124

    float acc[8][8];
    #pragma unroll
    for (int i = 0; i < 8; i++)
        #pragma unroll
        for (int j = 0; j < 8; j++) acc[i][j] = 0.f;

    for (int k0 = 0; k0 < K; k0 += 16) {
        float4 a0 = *(const float4*)(A + (size_t)(m0 + arow)      * K + k0 + acol);
        float4 a1 = *(const float4*)(A + (size_t)(m0 + arow + 64) * K + k0 + acol);
        float4 b0 = *(const float4*)(B + (size_t)(k0 + brow)     * N + n0 + bcol);
        float4 b1 = *(const float4*)(B + (size_t)(k0 + brow + 8) * N + n0 + bcol);
        __syncthreads();
        As[acol + 0][arow] = a0.x; As[acol + 1][arow] = a0.y;
        As[acol + 2][arow] = a0.z; As[acol + 3][arow] = a0.w;
        As[acol + 0][arow + 64] = a1.x; As[acol + 1][arow + 64] = a1.y;
        As[acol + 2][arow + 64] = a1.z; As[acol + 3][arow + 64] = a1.w;
        *(float4*)&Bs[brow][bcol]     = b0;
        *(float4*)&Bs[brow + 8][bcol] = b1;
        __syncthreads();

        #pragma unroll
        for (int kk = 0; kk < 16; kk++) {
            float af[8], bf[8];
            *(float4*)&af[0] = *(const float4*)&As[kk][ty * 8];
            *(float4*)&af[4] = *(const float4*)&As[kk][ty * 8 + 4];
            *(float4*)&bf[0] = *(const float4*)&Bs[kk][tx * 8];
            *(float4*)&bf[4] = *(const float4*)&Bs[kk][tx * 8 + 4];
            #pragma unroll
            for (int i = 0; i < 8; i++)
                #pragma unroll
                for (int j = 0; j < 8; j++)
                    acc[i][j] = fmaf(af[i], bf[j], acc[i][j]);
        }
    }

    #pragma unroll
    for (int i = 0; i < 8; i++) {
        float* cptr = C + (size_t)(m0 + ty * 8 + i) * N + n0 + tx * 8;
        *(float4*)cptr       = make_float4(acc[i][0], acc[i][1], acc[i][2], acc[i][3]);
        *(float4*)(cptr + 4) = make_float4(acc[i][4], acc[i][5], acc[i][6], acc[i][7]);
    }
}

// ============================================================================
// Fused RMSNorm + RoPE. One block of 128 threads per (token, head) row.
// X is (L, heads*HD) row-major; row = token*heads + head.
// ============================================================================
__global__ __launch_bounds__(128) void norm_rope_kernel(
    float* __restrict__ X, const float* __restrict__ scale,
    const int* __restrict__ positions, int heads)
{
    __shared__ float xs[HD];
    __shared__ float red[4];

    const int row   = blockIdx.x;
    const int token = row / heads;
    const int d     = threadIdx.x;
    float* ptr = X + (size_t)row * HD;

    float v  = ptr[d];
    float ss = v * v;
    #pragma unroll
    for (int off = 16; off > 0; off >>= 1)
        ss += __shfl_xor_sync(0xffffffffu, ss, off);
    if ((d & 31) == 0) red[d >> 5] = ss;
    __syncthreads();
    float tot = red[0] + red[1] + red[2] + red[3];
    float xn  = v * rsqrtf(tot * (1.0f / HD) + 1e-6f) * scale[d];
    xs[d] = xn;
    __syncthreads();

    const int   pos    = positions[token];
    const int   i      = d & 63;
    // timescale = 10000^(i/64)  ->  1/ts = exp2(-i * log2(10000)/64)
    const float inv_ts = exp2f(-(float)i * 0.20762050593046014f);
    const float ang    = (float)pos * inv_ts;
    float s, c;
    sincosf(ang, &s, &c);
    const float partner = xs[d ^ 64];
    const float out = (d < 64) ? (xn * c - partner * s)
                               : (xn * c + partner * s);
    ptr[d] = out;
}

// ============================================================================
// Sliding-window causal flash attention (fp32, online softmax).
// Block = (64 queries, 1 head); 256 threads as 16x16; 4x4 score micro-tile
// (strided: rows ty+16*ii, cols tx+16*jj), P staged through shared memory,
// 4x8 output micro-tile. GQA: q head h -> kv head h/4.
// ============================================================================
#define ATTN_SMEM_FLOATS (3 * 64 * 132 + 64 * 65)
#define ATTN_SMEM_BYTES  (ATTN_SMEM_FLOATS * 4)

__global__ __launch_bounds__(256) void attn_kernel(
    const float* __restrict__ Q, const float* __restrict__ K,
    const float* __restrict__ V, float* __restrict__ O)
{
    extern __shared__ float sm[];
    float (*Qs)[132] = (float (*)[132])sm;
    float (*Ks)[132] = (float (*)[132])(sm + 64 * 132);
    float (*Vs)[132] = (float (*)[132])(sm + 2 * 64 * 132);
    float (*Ps)[65]  = (float (*)[65]) (sm + 3 * 64 * 132);

    const int qt  = blockIdx.x;
    const int h   = blockIdx.y;
    const int q0  = qt * 64;
    const int g   = h >> 2;             // kv head (rep = 4)
    const int tid = threadIdx.x;
    const int ty  = tid >> 4;
    const int tx  = tid & 15;
    const int li  = tid >> 5;           // load row base (0..7)
    const int ld  = (tid & 31) * 4;     // load col (0..124)

    #pragma unroll
    for (int r = 0; r < 8; r++) {
        *(float4*)&Qs[li + r * 8][ld] =
            *(const float4*)(Q + (size_t)(q0 + li + r * 8) * (NH * HD) + h * HD + ld);
    }

    float m[4], l[4], o[4][8];
    #pragma unroll
    for (int ii = 0; ii < 4; ii++) {
        m[ii] = -1e30f; l[ii] = 0.f;
        #pragma unroll
        for (int c = 0; c < 8; c++) o[ii][c] = 0.f;
    }

    const int lo  = q0 - (WINDOW - 1);
    const int kt0 = (lo > 0) ? (lo >> 6) : 0;

    for (int kt = kt0; kt <= qt; kt++) {
        const int k0 = kt * 64;
        __syncthreads();
        #pragma unroll
        for (int r = 0; r < 8; r++) {
            const size_t off = (size_t)(k0 + li + r * 8) * (NKV * HD) + g * HD + ld;
            *(float4*)&Ks[li + r * 8][ld] = *(const float4*)(K + off);
            *(float4*)&Vs[li + r * 8][ld] = *(const float4*)(V + off);
        }
        __syncthreads();

        // ---- S = Q K^T ----
        float s[4][4];
        #pragma unroll
        for (int ii = 0; ii < 4; ii++)
            #pragma unroll
            for (int jj = 0; jj < 4; jj++) s[ii][jj] = 0.f;

        #pragma unroll 8
        for (int d = 0; d < HD; d += 4) {
            float4 qf[4], kf[4];
            #pragma unroll
            for (int ii = 0; ii < 4; ii++) qf[ii] = *(const float4*)&Qs[ty + 16 * ii][d];
            #pragma unroll
            for (int jj = 0; jj < 4; jj++) kf[jj] = *(const float4*)&Ks[tx + 16 * jj][d];
            #pragma unroll
            for (int ii = 0; ii < 4; ii++)
                #pragma unroll
                for (int jj = 0; jj < 4; jj++) {
                    s[ii][jj] = fmaf(qf[ii].x, kf[jj].x, s[ii][jj]);
                    s[ii][jj] = fmaf(qf[ii].y, kf[jj].y, s[ii][jj]);
                    s[ii][jj] = fmaf(qf[ii].z, kf[jj].z, s[ii][jj]);
                    s[ii][jj] = fmaf(qf[ii].w, kf[jj].w, s[ii][jj]);
                }
        }

        // ---- mask + online softmax ----
        #pragma unroll
        for (int ii = 0; ii < 4; ii++) {
            const int qi = q0 + ty + 16 * ii;
            float rmax = -1e30f;
            #pragma unroll
            for (int jj = 0; jj < 4; jj++) {
                const int kj = k0 + tx + 16 * jj;
                const bool ok = (kj <= qi) && (kj > qi - WINDOW);
                const float val = ok ? s[ii][jj] * SOFTMAX_SCALE : -1e30f;
                s[ii][jj] = val;
                rmax = fmaxf(rmax, val);
            }
            #pragma unroll
            for (int off = 8; off > 0; off >>= 1)
                rmax = fmaxf(rmax, __shfl_xor_sync(0xffffffffu, rmax, off));

            const float mn   = fmaxf(m[ii], rmax);
            const float corr = __expf(m[ii] - mn);
            m[ii] = mn;
            l[ii] *= corr;
            #pragma unroll
            for (int c = 0; c < 8; c++) o[ii][c] *= corr;

            float rsum = 0.f;
            #pragma unroll
            for (int jj = 0; jj < 4; jj++) {
                const float p = (s[ii][jj] < -1e29f) ? 0.f : __expf(s[ii][jj] - mn);
                Ps[ty + 16 * ii][tx + 16 * jj] = p;
                rsum += p;
            }
            #pragma unroll
            for (int off = 8; off > 0; off >>= 1)
                rsum += __shfl_xor_sync(0xffffffffu, rsum, off);
            l[ii] += rsum;
        }
        __syncthreads();

        // ---- O += P V ----
        #pragma unroll 4
        for (int j = 0; j < 64; j++) {
            const float4 v0 = *(const float4*)&Vs[j][tx * 8];
            const float4 v1 = *(const float4*)&Vs[j][tx * 8 + 4];
            #pragma unroll
            for (int ii = 0; ii < 4; ii++) {
                const float p = Ps[ty + 16 * ii][j];
                o[ii][0] = fmaf(p, v0.x, o[ii][0]);
                o[ii][1] = fmaf(p, v0.y, o[ii][1]);
                o[ii][2] = fmaf(p, v0.z, o[ii][2]);
                o[ii][3] = fmaf(p, v0.w, o[ii][3]);
                o[ii][4] = fmaf(p, v1.x, o[ii][4]);
                o[ii][5] = fmaf(p, v1.y, o[ii][5]);
                o[ii][6] = fmaf(p, v1.z, o[ii][6]);
                o[ii][7] = fmaf(p, v1.w, o[ii][7]);
            }
        }
    }

    #pragma unroll
    for (int ii = 0; ii < 4; ii++) {
        const float inv = 1.0f / l[ii];
        float* optr = O + (size_t)(q0 + ty + 16 * ii) * (NH * HD) + h * HD + tx * 8;
        *(float4*)optr = make_float4(o[ii][0] * inv, o[ii][1] * inv,
                                     o[ii][2] * inv, o[ii][3] * inv);
        *(float4*)(optr + 4) = make_float4(o[ii][4] * inv, o[ii][5] * inv,
                                           o[ii][6] * inv, o[ii][7] * inv);
    }
}

// ============================================================================
// launch
// ============================================================================
extern "C" void kernel_launch(void* const* d_in, const int* in_sizes, int n_in,
                              void* d_out, int out_size)
{
    const float* x   = (const float*)d_in[0];
    const int*   pos = (const int*)  d_in[1];
    const float* Wq  = (const float*)d_in[2];
    const float* Wk  = (const float*)d_in[3];
    const float* Wv  = (const float*)d_in[4];
    const float* Wo  = (const float*)d_in[5];
    const float* qsc = (const float*)d_in[6];
    const float* ksc = (const float*)d_in[7];
    float* out = (float*)d_out;

    float *Qp, *Kp, *Vp, *Ap;
    cudaGetSymbolAddress((void**)&Qp, g_Q);
    cudaGetSymbolAddress((void**)&Kp, g_K);
    cudaGetSymbolAddress((void**)&Vp, g_V);
    cudaGetSymbolAddress((void**)&Ap, g_att);

    // QKV projections
    sgemm_kernel<<<dim3(NH * HD / 128,  L_SEQ / 128), 256>>>(x, Wq, Qp, L_SEQ, NH * HD,  DMODEL);
    sgemm_kernel<<<dim3(NKV * HD / 128, L_SEQ / 128), 256>>>(x, Wk, Kp, L_SEQ, NKV * HD, DMODEL);
    sgemm_kernel<<<dim3(NKV * HD / 128, L_SEQ / 128), 256>>>(x, Wv, Vp, L_SEQ, NKV * HD, DMODEL);

    // RMSNorm + RoPE on Q and K
    norm_rope_kernel<<<L_SEQ * NH,  HD>>>(Qp, qsc, pos, NH);
    norm_rope_kernel<<<L_SEQ * NKV, HD>>>(Kp, ksc, pos, NKV);

    // sliding-window attention
    cudaFuncSetAttribute(attn_kernel, cudaFuncAttributeMaxDynamicSharedMemorySize,
                         ATTN_SMEM_BYTES);
    attn_kernel<<<dim3(L_SEQ / 64, NH), 256, ATTN_SMEM_BYTES>>>(Qp, Kp, Vp, Ap);

    // output projection straight into d_out
    sgemm_kernel<<<dim3(DMODEL / 128, L_SEQ / 128), 256>>>(Ap, Wo, out, L_SEQ, DMODEL, NH * HD);
}